// round 13
// baseline (speedup 1.0000x reference)
#include <cuda_runtime.h>
#include <cuda_bf16.h>
#include <cstdint>
#include <math.h>

// Problem dims
#define NB   8
#define NL   1024
#define NC   1024
#define NH   8
#define NCH  128
#define NBH  64
#define N3C  3072
#define QK_SCALE 0.29730177875068026f  // 128^(-1/4)
#define LOG2E    1.4426950408889634f

// Scratch (allocation-free rule: __device__ globals)
__device__ float          g_xn   [(size_t)NB * NL * NC];    // fp32 (residual)
__device__ __nv_bfloat16  g_xnh  [(size_t)NB * NL * NC];    // bf16 (GEMM A)
__device__ __nv_bfloat16  g_qkv  [(size_t)NB * NL * N3C];
__device__ __nv_bfloat16  g_attn [(size_t)NB * NL * NC];
__device__ __nv_bfloat16  g_wqkvh[(size_t)NC * N3C];        // bf16, native [K,N]
__device__ __nv_bfloat16  g_wouth[(size_t)NC * NC];         // bf16, native [K,N]

// ---------------------------------------------------------------------------
// Helpers (sm_80+ PTX only; target is plain compute_103 — no 'a' features)
// ---------------------------------------------------------------------------
__device__ __forceinline__ uint32_t smem_u32(const void* p) {
    uint32_t a;
    asm("{ .reg .u64 t; cvta.to.shared.u64 t, %1; cvt.u32.u64 %0, t; }" : "=r"(a) : "l"(p));
    return a;
}
__device__ __forceinline__ void cp16(uint32_t dst, const void* src) {
    asm volatile("cp.async.cg.shared.global [%0], [%1], 16;" :: "r"(dst), "l"(src));
}
#define CP_COMMIT() asm volatile("cp.async.commit_group;" ::: "memory")
#define CP_WAIT(n)  asm volatile("cp.async.wait_group %0;" :: "n"(n) : "memory")

__device__ __forceinline__ void mma_bf16(float* d, const uint32_t* a, const uint32_t* b) {
    asm volatile("mma.sync.aligned.m16n8k16.row.col.f32.bf16.bf16.f32 "
        "{%0,%1,%2,%3}, {%4,%5,%6,%7}, {%8,%9}, {%0,%1,%2,%3};"
        : "+f"(d[0]), "+f"(d[1]), "+f"(d[2]), "+f"(d[3])
        : "r"(a[0]), "r"(a[1]), "r"(a[2]), "r"(a[3]), "r"(b[0]), "r"(b[1]));
}
#define LDSM_X4(r, addr) \
    asm volatile("ldmatrix.sync.aligned.m8n8.x4.shared.b16 {%0,%1,%2,%3}, [%4];" \
        : "=r"((r)[0]), "=r"((r)[1]), "=r"((r)[2]), "=r"((r)[3]) : "r"(addr))
#define LDSM_X4_T(r, addr) \
    asm volatile("ldmatrix.sync.aligned.m8n8.x4.trans.shared.b16 {%0,%1,%2,%3}, [%4];" \
        : "=r"((r)[0]), "=r"((r)[1]), "=r"((r)[2]), "=r"((r)[3]) : "r"(addr))

__device__ __forceinline__ float ex2(float x) {
    float r;
    asm("ex2.approx.f32 %0, %1;" : "=f"(r) : "f"(x));
    return r;
}

// ---------------------------------------------------------------------------
// LayerNorm: fp32 out (residual) + bf16 out (GEMM operand)
// ---------------------------------------------------------------------------
__global__ void __launch_bounds__(256) ln_kernel(
    const float* __restrict__ x, const float* __restrict__ gamma,
    const float* __restrict__ beta, float* __restrict__ xn,
    __nv_bfloat16* __restrict__ xnh)
{
    int row = blockIdx.x;
    int t   = threadIdx.x;
    const float4* xr = reinterpret_cast<const float4*>(x + (size_t)row * NC);
    float4 v = xr[t];
    float s  = v.x + v.y + v.z + v.w;
    float ss = v.x*v.x + v.y*v.y + v.z*v.z + v.w*v.w;
    #pragma unroll
    for (int o = 16; o; o >>= 1) {
        s  += __shfl_xor_sync(0xffffffffu, s,  o);
        ss += __shfl_xor_sync(0xffffffffu, ss, o);
    }
    __shared__ float rs[8], rss[8], stat[2];
    int warp = t >> 5, lane = t & 31;
    if (lane == 0) { rs[warp] = s; rss[warp] = ss; }
    __syncthreads();
    if (t == 0) {
        float a = 0.f, b2 = 0.f;
        #pragma unroll
        for (int i = 0; i < 8; i++) { a += rs[i]; b2 += rss[i]; }
        float mu  = a * (1.0f / NC);
        float var = b2 * (1.0f / NC) - mu * mu;
        stat[0] = mu;
        stat[1] = rsqrtf(var + 1e-5f);
    }
    __syncthreads();
    float mu = stat[0], rstd = stat[1];
    float4 g4 = reinterpret_cast<const float4*>(gamma)[t];
    float4 b4 = reinterpret_cast<const float4*>(beta )[t];
    float4 o;
    o.x = (v.x - mu) * rstd * g4.x + b4.x;
    o.y = (v.y - mu) * rstd * g4.y + b4.y;
    o.z = (v.z - mu) * rstd * g4.z + b4.z;
    o.w = (v.w - mu) * rstd * g4.w + b4.w;
    reinterpret_cast<float4*>(xn + (size_t)row * NC)[t] = o;
    __nv_bfloat162 h0 = __float22bfloat162_rn(make_float2(o.x, o.y));
    __nv_bfloat162 h1 = __float22bfloat162_rn(make_float2(o.z, o.w));
    uint2 u; u.x = *(uint32_t*)&h0; u.y = *(uint32_t*)&h1;
    *reinterpret_cast<uint2*>(xnh + (size_t)row * NC + t * 4) = u;
}

// ---------------------------------------------------------------------------
// Elementwise fp32 -> bf16 convert (weights; layout preserved)
// ---------------------------------------------------------------------------
__global__ void __launch_bounds__(256) cvt_kernel(
    const float* __restrict__ src, __nv_bfloat16* __restrict__ dst)
{
    size_t i = ((size_t)blockIdx.x * 256 + threadIdx.x) * 8;
    float4 a = *(const float4*)(src + i);
    float4 b = *(const float4*)(src + i + 4);
    __nv_bfloat162 h0 = __float22bfloat162_rn(make_float2(a.x, a.y));
    __nv_bfloat162 h1 = __float22bfloat162_rn(make_float2(a.z, a.w));
    __nv_bfloat162 h2 = __float22bfloat162_rn(make_float2(b.x, b.y));
    __nv_bfloat162 h3 = __float22bfloat162_rn(make_float2(b.z, b.w));
    uint4 u;
    u.x = *(uint32_t*)&h0; u.y = *(uint32_t*)&h1;
    u.z = *(uint32_t*)&h2; u.w = *(uint32_t*)&h3;
    *reinterpret_cast<uint4*>(dst + i) = u;
}

// ---------------------------------------------------------------------------
// bf16 mma.sync GEMM: C[M,N] = A[M,K] @ B[K,N] (+bias; MODE epilogue)
// CTA 128x128, BK=64, **4 warps of 64x64** (halved smem reads/MAC vs 8x 64x32),
// 128 threads, 2 CTA/SM, 3-stage cp.async, single barrier per chunk.
// MODE 0: bf16 out, q cols *= QK_SCALE*LOG2E, k cols *= QK_SCALE.
// MODE 1: fp32 out, += bias + resid.
// ---------------------------------------------------------------------------
#define BM 128
#define BN 128
#define BK 64
#define KTOT 1024
#define NCHUNK (KTOT / BK)              // 16
#define GST 72                          // A smem halves stride (64+8)
#define BNS 136                         // B smem halves stride (128+8)
#define STAGE_H (BM * GST + BK * BNS)   // 17920 halves
#define SMEM_GEMM (3 * STAGE_H * 2)     // 107520 bytes

template <int MODE>
__global__ void __launch_bounds__(128, 2) gemm_bf16_kernel(
    const __nv_bfloat16* __restrict__ A, const __nv_bfloat16* __restrict__ Bw,
    const float* __restrict__ bias, const float* __restrict__ resid,
    void* __restrict__ Cm, int N)
{
    extern __shared__ __align__(16) __nv_bfloat16 smh[];
    uint32_t sbase = smem_u32(smh);
    int tid = threadIdx.x;
    int wid = tid >> 5, lane = tid & 31;
    int g = lane >> 2, q = lane & 3;
    const int bm = blockIdx.y * BM;
    const int bn = blockIdx.x * BN;
    const int warpM = (wid >> 1) * 64;
    const int warpN = (wid & 1) * 64;

    // ldmatrix lane address components
    int a_r = (lane & 7) | (((lane >> 3) & 1) << 3);   // A row within 16
    int a_c = (lane >> 4) << 3;                        // A k-halves offset
    int v_r = (lane & 7) | (((lane >> 3) & 1) << 3);   // B(k) row select
    int v_c = (lane >> 4) << 3;                        // B(n) +8 select

    auto load_chunk = [&](int kk, int stg) {
        uint32_t sA = sbase + (uint32_t)(stg * STAGE_H) * 2;
        uint32_t sB = sA + (uint32_t)(BM * GST) * 2;
        #pragma unroll
        for (int i = 0; i < 8; i++) {     // A: 128 rows x 8 chunks(8h)
            int f = i * 128 + tid;
            int r = f >> 3, c = f & 7;
            cp16(sA + (uint32_t)(r * GST + c * 8) * 2,
                 A + (size_t)(bm + r) * KTOT + kk + c * 8);
        }
        #pragma unroll
        for (int i = 0; i < 8; i++) {     // B: 64 k-rows x 16 chunks(8h)
            int f = i * 128 + tid;
            int r = f >> 4, c = f & 15;
            cp16(sB + (uint32_t)(r * BNS + c * 8) * 2,
                 Bw + (size_t)(kk + r) * N + bn + c * 8);
        }
        CP_COMMIT();
    };

    float accf[4][8][4];                  // 128 regs: 4 m-tiles x 8 n-tiles
    #pragma unroll
    for (int mt = 0; mt < 4; mt++)
        #pragma unroll
        for (int nt = 0; nt < 8; nt++)
            #pragma unroll
            for (int r = 0; r < 4; r++) accf[mt][nt][r] = 0.f;

    load_chunk(0, 0);
    load_chunk(BK, 1);

    for (int c = 0; c < NCHUNK; c++) {
        if (c < NCHUNK - 1) CP_WAIT(1); else CP_WAIT(0);
        __syncthreads();
        if (c + 2 < NCHUNK) load_chunk((c + 2) * BK, (c + 2) % 3);
        uint32_t sA = sbase + (uint32_t)((c % 3) * STAGE_H) * 2;
        uint32_t sB = sA + (uint32_t)(BM * GST) * 2;
        #pragma unroll
        for (int ks = 0; ks < 4; ks++) {
            int k0 = ks * 16;
            uint32_t afr[4][4], bfr[4][4];
            #pragma unroll
            for (int mt = 0; mt < 4; mt++)
                LDSM_X4(afr[mt], sA + (uint32_t)((warpM + mt * 16 + a_r) * GST + k0 + a_c) * 2);
            #pragma unroll
            for (int np = 0; np < 4; np++)
                LDSM_X4_T(bfr[np], sB + (uint32_t)((k0 + v_r) * BNS + warpN + np * 16 + v_c) * 2);
            #pragma unroll
            for (int mt = 0; mt < 4; mt++)
                #pragma unroll
                for (int np = 0; np < 4; np++) {
                    mma_bf16(accf[mt][np * 2 + 0], afr[mt], &bfr[np][0]);
                    mma_bf16(accf[mt][np * 2 + 1], afr[mt], &bfr[np][2]);
                }
        }
    }

    #pragma unroll
    for (int mt = 0; mt < 4; mt++) {
        int row0 = bm + warpM + mt * 16 + g;
        #pragma unroll
        for (int nt = 0; nt < 8; nt++) {
            int col = bn + warpN + nt * 8 + q * 2;
            float2 bb = *(const float2*)&bias[col];
            float mscale = 1.0f;
            if (MODE == 0)
                mscale = (col < NC) ? (QK_SCALE * LOG2E)
                                    : ((col < 2 * NC) ? QK_SCALE : 1.0f);
            #pragma unroll
            for (int h = 0; h < 2; h++) {
                int row = row0 + h * 8;
                float2 o;
                o.x = accf[mt][nt][h * 2 + 0] + bb.x;
                o.y = accf[mt][nt][h * 2 + 1] + bb.y;
                if (MODE == 0) {
                    o.x *= mscale; o.y *= mscale;
                    __nv_bfloat162 hb = __float22bfloat162_rn(o);
                    *reinterpret_cast<__nv_bfloat162*>(
                        (__nv_bfloat16*)Cm + (size_t)row * N + col) = hb;
                } else {
                    float2 rr = *(const float2*)&resid[(size_t)row * NC + col];
                    o.x += rr.x; o.y += rr.y;
                    *reinterpret_cast<float2*>((float*)Cm + (size_t)row * N + col) = o;
                }
            }
        }
    }
}

// ---------------------------------------------------------------------------
// bf16 mma.sync flash attention (verified R11 config, unchanged):
// RAW-RESHAPED layout, no-max log2 softmax, BMA=128/BNA=64, 256 threads,
// cp.async K (pre-barrier) / V (behind S-phase) / Q.
// ---------------------------------------------------------------------------
#define BMA 128
#define BNA 64
#define ATSH 136            // Q/K/V smem halves stride (128+8)
#define PSTH 72             // P smem halves stride (64+8)
#define QOFFH  0
#define KOFFH  (BMA * ATSH)
#define VOFFH  (KOFFH + BNA * ATSH)
#define PSOFFH (VOFFH + BNA * ATSH)
#define ATT_SMEM ((PSOFFH + BMA * PSTH) * 2)   // 88064 B

__global__ void __launch_bounds__(256, 2) attn_kernel(
    const __nv_bfloat16* __restrict__ qkv, __nv_bfloat16* __restrict__ outp)
{
    extern __shared__ __align__(16) __nv_bfloat16 smh[];
    uint32_t uQ = smem_u32(smh + QOFFH);
    uint32_t uK = smem_u32(smh + KOFFH);
    uint32_t uV = smem_u32(smh + VOFFH);
    __nv_bfloat16* Ps = smh + PSOFFH;
    uint32_t uP = smem_u32(Ps);

    int tid = threadIdx.x;
    int wid = tid >> 5, lane = tid & 31;
    int g = lane >> 2, q = lane & 3;
    int bh  = blockIdx.y;
    int m0  = blockIdx.x * BMA;
    int bb  = bh >> 3, hh = bh & 7;
    const __nv_bfloat16* base = qkv + (size_t)(bb * 1024 + hh * 128) * N3C;
    const int warpM = wid * 16;

    int a_r = (lane & 7) | (((lane >> 3) & 1) << 3);
    int a_c = (lane >> 4) << 3;
    int b_r = (lane & 7) | (((lane >> 4) & 1) << 3);
    int b_c = ((lane >> 3) & 1) << 3;
    int v_r = (lane & 7) | (((lane >> 3) & 1) << 3);
    int v_c = (lane >> 4) << 3;

    // Q tile -> smem via cp.async
    #pragma unroll
    for (int i = 0; i < 8; i++) {
        int f = i * 256 + tid;
        int r = f >> 4, c8 = f & 15;
        int l2 = m0 + r;
        cp16(uQ + (uint32_t)(r * ATSH + c8 * 8) * 2,
             base + (size_t)(l2 >> 3) * N3C + ((l2 & 7) << 7) + c8 * 8);
    }
    CP_COMMIT();

    float Oacc[16][4];
    float lsum[2] = {0.f, 0.f};
    #pragma unroll
    for (int nt = 0; nt < 16; nt++)
        #pragma unroll
        for (int r = 0; r < 4; r++) Oacc[nt][r] = 0.f;

    for (int kt = 0; kt < NL / BNA; kt++) {
        int n0 = kt * BNA;

        // Issue K loads (Ks free: prior S-phase reads done pre-post-P barrier)
        #pragma unroll
        for (int i = 0; i < 4; i++) {
            int f = i * 256 + tid;
            int r = f >> 4, c8 = f & 15;
            int n = n0 + r;
            cp16(uK + (uint32_t)(r * ATSH + c8 * 8) * 2,
                 base + (size_t)(n >> 3) * N3C + NC + ((n & 7) << 7) + c8 * 8);
        }
        CP_COMMIT();

        __syncthreads();   // prev PV done (Vs, Ps free)

        // Issue V loads — land during S-phase compute
        #pragma unroll
        for (int i = 0; i < 4; i++) {
            int f = i * 256 + tid;
            int r = f >> 4, c8 = f & 15;
            int n = n0 + r;
            cp16(uV + (uint32_t)(r * ATSH + c8 * 8) * 2,
                 base + (size_t)(n >> 3) * N3C + 2 * NC + ((n & 7) << 7) + c8 * 8);
        }
        CP_COMMIT();

        CP_WAIT(1);        // K (and Q, first iter) arrived (this thread)
        __syncthreads();   // ... and all threads

        // S = Q K^T : 8 ksteps of k16 over d=128
        float Sacc[8][4];
        #pragma unroll
        for (int nt = 0; nt < 8; nt++)
            #pragma unroll
            for (int r = 0; r < 4; r++) Sacc[nt][r] = 0.f;
        #pragma unroll
        for (int ks = 0; ks < 8; ks++) {
            int k0 = ks * 16;
            uint32_t afr[4], bfr[4][4];
            LDSM_X4(afr, uQ + (uint32_t)((warpM + a_r) * ATSH + k0 + a_c) * 2);
            #pragma unroll
            for (int np = 0; np < 4; np++)
                LDSM_X4(bfr[np], uK + (uint32_t)((np * 16 + b_r) * ATSH + k0 + b_c) * 2);
            #pragma unroll
            for (int np = 0; np < 4; np++) {
                mma_bf16(Sacc[np * 2 + 0], afr, &bfr[np][0]);
                mma_bf16(Sacc[np * 2 + 1], afr, &bfr[np][2]);
            }
        }

        CP_WAIT(0);        // V arrived (this thread)

        // P = 2^S (log2-domain, no max), bf16 store, fp32 row sums
        #pragma unroll
        for (int h = 0; h < 2; h++) {
            float ls = 0.f;
            int prow = (warpM + g + 8 * h) * PSTH + 2 * q;
            #pragma unroll
            for (int nt = 0; nt < 8; nt++) {
                float e0 = ex2(Sacc[nt][2 * h + 0]);
                float e1 = ex2(Sacc[nt][2 * h + 1]);
                ls += e0 + e1;
                *reinterpret_cast<__nv_bfloat162*>(&Ps[prow + nt * 8]) =
                    __float22bfloat162_rn(make_float2(e0, e1));
            }
            ls += __shfl_xor_sync(0xffffffffu, ls, 1);
            ls += __shfl_xor_sync(0xffffffffu, ls, 2);
            lsum[h] += ls;
        }
        __syncthreads();   // P + V visible to all

        // O += P @ V : 4 ksteps of k16 over n=64; V via ldmatrix.trans
        #pragma unroll
        for (int kv = 0; kv < 4; kv++) {
            int k0 = kv * 16;
            uint32_t afr[4];
            LDSM_X4(afr, uP + (uint32_t)((warpM + a_r) * PSTH + k0 + a_c) * 2);
            #pragma unroll
            for (int dp = 0; dp < 8; dp++) {
                uint32_t vfr[4];
                LDSM_X4_T(vfr, uV + (uint32_t)((k0 + v_r) * ATSH + dp * 16 + v_c) * 2);
                mma_bf16(Oacc[dp * 2 + 0], afr, &vfr[0]);
                mma_bf16(Oacc[dp * 2 + 1], afr, &vfr[2]);
            }
        }
    }

    // Epilogue: out = O / lsum, bf16 (flat layout == raw reshape back)
    #pragma unroll
    for (int h = 0; h < 2; h++) {
        float inv = 1.0f / lsum[h];
        int row = m0 + warpM + g + 8 * h;
        __nv_bfloat16* dst = outp + (size_t)bh * (NL * NCH) + (size_t)row * NCH + 2 * q;
        #pragma unroll
        for (int nt = 0; nt < 16; nt++) {
            float2 w;
            w.x = Oacc[nt][2 * h + 0] * inv;
            w.y = Oacc[nt][2 * h + 1] * inv;
            *reinterpret_cast<__nv_bfloat162*>(&dst[nt * 8]) = __float22bfloat162_rn(w);
        }
    }
}

// ---------------------------------------------------------------------------
extern "C" void kernel_launch(void* const* d_in, const int* in_sizes, int n_in,
                              void* d_out, int out_size)
{
    const float* x     = (const float*)d_in[0];
    const float* ln_g  = (const float*)d_in[1];
    const float* ln_b  = (const float*)d_in[2];
    const float* w_qkv = (const float*)d_in[3];
    const float* b_qkv = (const float*)d_in[4];
    const float* w_out = (const float*)d_in[5];
    const float* b_out = (const float*)d_in[6];
    float* out = (float*)d_out;

    float *xn;
    __nv_bfloat16 *xnh, *qkvb, *attnb, *wqkvh, *wouth;
    cudaGetSymbolAddress((void**)&xn,    g_xn);
    cudaGetSymbolAddress((void**)&xnh,   g_xnh);
    cudaGetSymbolAddress((void**)&qkvb,  g_qkv);
    cudaGetSymbolAddress((void**)&attnb, g_attn);
    cudaGetSymbolAddress((void**)&wqkvh, g_wqkvh);
    cudaGetSymbolAddress((void**)&wouth, g_wouth);

    cudaFuncSetAttribute(gemm_bf16_kernel<0>,
                         cudaFuncAttributeMaxDynamicSharedMemorySize, SMEM_GEMM);
    cudaFuncSetAttribute(gemm_bf16_kernel<1>,
                         cudaFuncAttributeMaxDynamicSharedMemorySize, SMEM_GEMM);
    cudaFuncSetAttribute(attn_kernel,
                         cudaFuncAttributeMaxDynamicSharedMemorySize, ATT_SMEM);

    // 0) Convert weights fp32 -> bf16 (native [K,N] layout)
    cvt_kernel<<<(NC * N3C) / 2048, 256>>>(w_qkv, wqkvh);
    cvt_kernel<<<(NC * NC)  / 2048, 256>>>(w_out, wouth);

    // 1) LayerNorm (fp32 + bf16 outputs)
    ln_kernel<<<NB * NL, 256>>>(x, ln_g, ln_b, xn, xnh);

    // 2) QKV projection (bf16 mma; q cols pre-scaled by log2e) -> bf16
    gemm_bf16_kernel<0><<<dim3(N3C / BN, (NB * NL) / BM), 128, SMEM_GEMM>>>(
        xnh, wqkvh, b_qkv, nullptr, qkvb, N3C);

    // 3) Attention (bf16 mma, log2-domain no-max softmax) -> bf16
    attn_kernel<<<dim3(NL / BMA, NBH), 256, ATT_SMEM>>>(qkvb, attnb);

    // 4) Output projection + bias + residual(fp32 xn) -> fp32
    gemm_bf16_kernel<1><<<dim3(NC / BN, (NB * NL) / BM), 128, SMEM_GEMM>>>(
        attnb, wouth, b_out, xn, out, NC);
}

// round 16
// speedup vs baseline: 1.0267x; 1.0267x over previous
#include <cuda_runtime.h>
#include <cuda_bf16.h>
#include <cstdint>
#include <math.h>

// Problem dims
#define NB   8
#define NL   1024
#define NC   1024
#define NH   8
#define NCH  128
#define NBH  64
#define N3C  3072
#define QK_SCALE 0.29730177875068026f  // 128^(-1/4)
#define LOG2E    1.4426950408889634f

// Scratch (allocation-free rule: __device__ globals)
__device__ float          g_xn   [(size_t)NB * NL * NC];    // fp32 (residual)
__device__ __nv_bfloat16  g_xnh  [(size_t)NB * NL * NC];    // bf16 (GEMM A)
__device__ __nv_bfloat16  g_qkv  [(size_t)NB * NL * N3C];
__device__ __nv_bfloat16  g_attn [(size_t)NB * NL * NC];
__device__ __nv_bfloat16  g_wqkvh[(size_t)NC * N3C];        // bf16, native [K,N]
__device__ __nv_bfloat16  g_wouth[(size_t)NC * NC];         // bf16, native [K,N]

// ---------------------------------------------------------------------------
// Helpers (sm_80+ PTX only; target is plain compute_103 — no 'a' features)
// ---------------------------------------------------------------------------
__device__ __forceinline__ uint32_t smem_u32(const void* p) {
    uint32_t a;
    asm("{ .reg .u64 t; cvta.to.shared.u64 t, %1; cvt.u32.u64 %0, t; }" : "=r"(a) : "l"(p));
    return a;
}
__device__ __forceinline__ void cp16(uint32_t dst, const void* src) {
    asm volatile("cp.async.cg.shared.global [%0], [%1], 16;" :: "r"(dst), "l"(src));
}
#define CP_COMMIT() asm volatile("cp.async.commit_group;" ::: "memory")
#define CP_WAIT(n)  asm volatile("cp.async.wait_group %0;" :: "n"(n) : "memory")

__device__ __forceinline__ void mma_bf16(float* d, const uint32_t* a, const uint32_t* b) {
    asm volatile("mma.sync.aligned.m16n8k16.row.col.f32.bf16.bf16.f32 "
        "{%0,%1,%2,%3}, {%4,%5,%6,%7}, {%8,%9}, {%0,%1,%2,%3};"
        : "+f"(d[0]), "+f"(d[1]), "+f"(d[2]), "+f"(d[3])
        : "r"(a[0]), "r"(a[1]), "r"(a[2]), "r"(a[3]), "r"(b[0]), "r"(b[1]));
}
#define LDSM_X4(r, addr) \
    asm volatile("ldmatrix.sync.aligned.m8n8.x4.shared.b16 {%0,%1,%2,%3}, [%4];" \
        : "=r"((r)[0]), "=r"((r)[1]), "=r"((r)[2]), "=r"((r)[3]) : "r"(addr))
#define LDSM_X4_T(r, addr) \
    asm volatile("ldmatrix.sync.aligned.m8n8.x4.trans.shared.b16 {%0,%1,%2,%3}, [%4];" \
        : "=r"((r)[0]), "=r"((r)[1]), "=r"((r)[2]), "=r"((r)[3]) : "r"(addr))

__device__ __forceinline__ float ex2(float x) {
    float r;
    asm("ex2.approx.f32 %0, %1;" : "=f"(r) : "f"(x));
    return r;
}
__device__ __forceinline__ uint32_t pack_bf16(float a, float b) {
    __nv_bfloat162 h = __float22bfloat162_rn(make_float2(a, b));
    return *(uint32_t*)&h;
}

// ---------------------------------------------------------------------------
// LayerNorm: fp32 out (residual) + bf16 out (GEMM operand)
// ---------------------------------------------------------------------------
__global__ void __launch_bounds__(256) ln_kernel(
    const float* __restrict__ x, const float* __restrict__ gamma,
    const float* __restrict__ beta, float* __restrict__ xn,
    __nv_bfloat16* __restrict__ xnh)
{
    int row = blockIdx.x;
    int t   = threadIdx.x;
    const float4* xr = reinterpret_cast<const float4*>(x + (size_t)row * NC);
    float4 v = xr[t];
    float s  = v.x + v.y + v.z + v.w;
    float ss = v.x*v.x + v.y*v.y + v.z*v.z + v.w*v.w;
    #pragma unroll
    for (int o = 16; o; o >>= 1) {
        s  += __shfl_xor_sync(0xffffffffu, s,  o);
        ss += __shfl_xor_sync(0xffffffffu, ss, o);
    }
    __shared__ float rs[8], rss[8], stat[2];
    int warp = t >> 5, lane = t & 31;
    if (lane == 0) { rs[warp] = s; rss[warp] = ss; }
    __syncthreads();
    if (t == 0) {
        float a = 0.f, b2 = 0.f;
        #pragma unroll
        for (int i = 0; i < 8; i++) { a += rs[i]; b2 += rss[i]; }
        float mu  = a * (1.0f / NC);
        float var = b2 * (1.0f / NC) - mu * mu;
        stat[0] = mu;
        stat[1] = rsqrtf(var + 1e-5f);
    }
    __syncthreads();
    float mu = stat[0], rstd = stat[1];
    float4 g4 = reinterpret_cast<const float4*>(gamma)[t];
    float4 b4 = reinterpret_cast<const float4*>(beta )[t];
    float4 o;
    o.x = (v.x - mu) * rstd * g4.x + b4.x;
    o.y = (v.y - mu) * rstd * g4.y + b4.y;
    o.z = (v.z - mu) * rstd * g4.z + b4.z;
    o.w = (v.w - mu) * rstd * g4.w + b4.w;
    reinterpret_cast<float4*>(xn + (size_t)row * NC)[t] = o;
    __nv_bfloat162 h0 = __float22bfloat162_rn(make_float2(o.x, o.y));
    __nv_bfloat162 h1 = __float22bfloat162_rn(make_float2(o.z, o.w));
    uint2 u; u.x = *(uint32_t*)&h0; u.y = *(uint32_t*)&h1;
    *reinterpret_cast<uint2*>(xnh + (size_t)row * NC + t * 4) = u;
}

// ---------------------------------------------------------------------------
// Elementwise fp32 -> bf16 convert (weights; layout preserved)
// ---------------------------------------------------------------------------
__global__ void __launch_bounds__(256) cvt_kernel(
    const float* __restrict__ src, __nv_bfloat16* __restrict__ dst)
{
    size_t i = ((size_t)blockIdx.x * 256 + threadIdx.x) * 8;
    float4 a = *(const float4*)(src + i);
    float4 b = *(const float4*)(src + i + 4);
    __nv_bfloat162 h0 = __float22bfloat162_rn(make_float2(a.x, a.y));
    __nv_bfloat162 h1 = __float22bfloat162_rn(make_float2(a.z, a.w));
    __nv_bfloat162 h2 = __float22bfloat162_rn(make_float2(b.x, b.y));
    __nv_bfloat162 h3 = __float22bfloat162_rn(make_float2(b.z, b.w));
    uint4 u;
    u.x = *(uint32_t*)&h0; u.y = *(uint32_t*)&h1;
    u.z = *(uint32_t*)&h2; u.w = *(uint32_t*)&h3;
    *reinterpret_cast<uint4*>(dst + i) = u;
}

// ---------------------------------------------------------------------------
// bf16 mma.sync GEMM (R11 best config): C = A[M,K] @ B[K,N] (+bias; MODE)
// CTA 128x128, BK=64, 8 warps (2x4), warp 64x32, 3-stage cp.async, single
// barrier per chunk, fragment double-buffering across k-steps.
// MODE 0: bf16 out, q cols *= QK_SCALE*LOG2E, k cols *= QK_SCALE.
// MODE 1: fp32 out, += bias + resid.
// ---------------------------------------------------------------------------
#define BM 128
#define BN 128
#define BK 64
#define KTOT 1024
#define NCHUNK (KTOT / BK)              // 16
#define GST 72                          // A smem halves stride (64+8)
#define BNS 136                         // B smem halves stride (128+8)
#define STAGE_H (BM * GST + BK * BNS)   // 17920 halves
#define SMEM_GEMM (3 * STAGE_H * 2)     // 107520 bytes

template <int MODE>
__global__ void __launch_bounds__(256, 2) gemm_bf16_kernel(
    const __nv_bfloat16* __restrict__ A, const __nv_bfloat16* __restrict__ Bw,
    const float* __restrict__ bias, const float* __restrict__ resid,
    void* __restrict__ Cm, int N)
{
    extern __shared__ __align__(16) __nv_bfloat16 smh[];
    uint32_t sbase = smem_u32(smh);
    int tid = threadIdx.x;
    int wid = tid >> 5, lane = tid & 31;
    int g = lane >> 2, q = lane & 3;
    const int bm = blockIdx.y * BM;
    const int bn = blockIdx.x * BN;
    const int warpM = (wid >> 2) * 64;
    const int warpN = (wid & 3) * 32;

    int a_r = (lane & 7) | (((lane >> 3) & 1) << 3);
    int a_c = (lane >> 4) << 3;
    int v_r = (lane & 7) | (((lane >> 3) & 1) << 3);
    int v_c = (lane >> 4) << 3;

    auto load_chunk = [&](int kk, int stg) {
        uint32_t sA = sbase + (uint32_t)(stg * STAGE_H) * 2;
        uint32_t sB = sA + (uint32_t)(BM * GST) * 2;
        #pragma unroll
        for (int i = 0; i < 4; i++) {
            int f = i * 256 + tid;
            int r = f >> 3, c = f & 7;
            cp16(sA + (uint32_t)(r * GST + c * 8) * 2,
                 A + (size_t)(bm + r) * KTOT + kk + c * 8);
        }
        #pragma unroll
        for (int i = 0; i < 4; i++) {
            int f = i * 256 + tid;
            int r = f >> 4, c = f & 15;
            cp16(sB + (uint32_t)(r * BNS + c * 8) * 2,
                 Bw + (size_t)(kk + r) * N + bn + c * 8);
        }
        CP_COMMIT();
    };

    float accf[4][4][4];
    #pragma unroll
    for (int mt = 0; mt < 4; mt++)
        #pragma unroll
        for (int nt = 0; nt < 4; nt++)
            #pragma unroll
            for (int r = 0; r < 4; r++) accf[mt][nt][r] = 0.f;

    load_chunk(0, 0);
    load_chunk(BK, 1);

    for (int c = 0; c < NCHUNK; c++) {
        if (c < NCHUNK - 1) CP_WAIT(1); else CP_WAIT(0);
        __syncthreads();
        if (c + 2 < NCHUNK) load_chunk((c + 2) * BK, (c + 2) % 3);
        uint32_t sA = sbase + (uint32_t)((c % 3) * STAGE_H) * 2;
        uint32_t sB = sA + (uint32_t)(BM * GST) * 2;
        uint32_t aAddr = sA + (uint32_t)((warpM + a_r) * GST + a_c) * 2;
        uint32_t bAddr = sB + (uint32_t)(v_r * BNS + warpN + v_c) * 2;

        uint32_t afr[2][4][4], bfr[2][2][4];
        #pragma unroll
        for (int mt = 0; mt < 4; mt++)
            LDSM_X4(afr[0][mt], aAddr + (uint32_t)(mt * 16 * GST) * 2);
        #pragma unroll
        for (int np = 0; np < 2; np++)
            LDSM_X4_T(bfr[0][np], bAddr + (uint32_t)(np * 16) * 2);

        #pragma unroll
        for (int ks = 0; ks < 4; ks++) {
            int cur = ks & 1, nxt = cur ^ 1;
            if (ks < 3) {
                uint32_t aA = aAddr + (uint32_t)((ks + 1) * 16) * 2;
                uint32_t bA = bAddr + (uint32_t)((ks + 1) * 16 * BNS) * 2;
                #pragma unroll
                for (int mt = 0; mt < 4; mt++)
                    LDSM_X4(afr[nxt][mt], aA + (uint32_t)(mt * 16 * GST) * 2);
                #pragma unroll
                for (int np = 0; np < 2; np++)
                    LDSM_X4_T(bfr[nxt][np], bA + (uint32_t)(np * 16) * 2);
            }
            #pragma unroll
            for (int mt = 0; mt < 4; mt++)
                #pragma unroll
                for (int np = 0; np < 2; np++) {
                    mma_bf16(accf[mt][np * 2 + 0], afr[cur][mt], &bfr[cur][np][0]);
                    mma_bf16(accf[mt][np * 2 + 1], afr[cur][mt], &bfr[cur][np][2]);
                }
        }
    }

    #pragma unroll
    for (int mt = 0; mt < 4; mt++) {
        int row0 = bm + warpM + mt * 16 + g;
        #pragma unroll
        for (int nt = 0; nt < 4; nt++) {
            int col = bn + warpN + nt * 8 + q * 2;
            float2 bb = *(const float2*)&bias[col];
            float mscale = 1.0f;
            if (MODE == 0)
                mscale = (col < NC) ? (QK_SCALE * LOG2E)
                                    : ((col < 2 * NC) ? QK_SCALE : 1.0f);
            #pragma unroll
            for (int h = 0; h < 2; h++) {
                int row = row0 + h * 8;
                float2 o;
                o.x = accf[mt][nt][h * 2 + 0] + bb.x;
                o.y = accf[mt][nt][h * 2 + 1] + bb.y;
                if (MODE == 0) {
                    o.x *= mscale; o.y *= mscale;
                    __nv_bfloat162 hb = __float22bfloat162_rn(o);
                    *reinterpret_cast<__nv_bfloat162*>(
                        (__nv_bfloat16*)Cm + (size_t)row * N + col) = hb;
                } else {
                    float2 rr = *(const float2*)&resid[(size_t)row * NC + col];
                    o.x += rr.x; o.y += rr.y;
                    *reinterpret_cast<float2*>((float*)Cm + (size_t)row * N + col) = o;
                }
            }
        }
    }
}

// ---------------------------------------------------------------------------
// bf16 mma.sync flash attention v2: RAW-RESHAPED layout, no-max log2 softmax.
// BMA=128 q, BNA=64 kv, 256 thr = 8 warps x 16 m-rows.
// REGISTER-RESIDENT P: the m16n8k16 A-fragment layout equals the S-accumulator
// layout, so P=2^S is packed to bf16 in registers — no P smem, no P ldsm.
// K and V double-buffered, issued one iteration ahead as a single cp.async
// group -> exactly ONE __syncthreads per kv-iteration.
// ---------------------------------------------------------------------------
#define BMA 128
#define BNA 64
#define ATSH 136                       // smem halves stride (128+8)
#define KVB_H (BNA * ATSH)             // 8704 halves per K or V buffer
#define QOFFH  0
#define K0OFFH (BMA * ATSH)            // 17408
#define V0OFFH (K0OFFH + 2 * KVB_H)    // 34816
#define ATT_SMEM ((V0OFFH + 2 * KVB_H) * 2)   // 104448 B

__global__ void __launch_bounds__(256, 2) attn_kernel(
    const __nv_bfloat16* __restrict__ qkv, __nv_bfloat16* __restrict__ outp)
{
    extern __shared__ __align__(16) __nv_bfloat16 smh[];
    uint32_t uQ  = smem_u32(smh + QOFFH);
    uint32_t uK0 = smem_u32(smh + K0OFFH);
    uint32_t uV0 = smem_u32(smh + V0OFFH);

    int tid = threadIdx.x;
    int wid = tid >> 5, lane = tid & 31;
    int g = lane >> 2, q = lane & 3;
    int bh  = blockIdx.y;
    int m0  = blockIdx.x * BMA;
    int bb  = bh >> 3, hh = bh & 7;
    const __nv_bfloat16* base = qkv + (size_t)(bb * 1024 + hh * 128) * N3C;
    const int warpM = wid * 16;

    int a_r = (lane & 7) | (((lane >> 3) & 1) << 3);
    int a_c = (lane >> 4) << 3;
    int b_r = (lane & 7) | (((lane >> 4) & 1) << 3);
    int b_c = ((lane >> 3) & 1) << 3;
    int v_r = (lane & 7) | (((lane >> 3) & 1) << 3);
    int v_c = (lane >> 4) << 3;

    // Q tile -> smem via cp.async (group 1)
    #pragma unroll
    for (int i = 0; i < 8; i++) {
        int f = i * 256 + tid;
        int r = f >> 4, c8 = f & 15;
        int l2 = m0 + r;
        cp16(uQ + (uint32_t)(r * ATSH + c8 * 8) * 2,
             base + (size_t)(l2 >> 3) * N3C + ((l2 & 7) << 7) + c8 * 8);
    }
    CP_COMMIT();

    // K+V for a kv-tile -> buffer buf, as ONE commit group
    auto issue_kv = [&](int n0, int buf) {
        uint32_t kb = uK0 + (uint32_t)(buf * KVB_H) * 2;
        uint32_t vb = uV0 + (uint32_t)(buf * KVB_H) * 2;
        #pragma unroll
        for (int i = 0; i < 4; i++) {
            int f = i * 256 + tid;
            int r = f >> 4, c8 = f & 15;
            int n = n0 + r;
            const __nv_bfloat16* s =
                base + (size_t)(n >> 3) * N3C + ((n & 7) << 7) + c8 * 8;
            cp16(kb + (uint32_t)(r * ATSH + c8 * 8) * 2, s + NC);
            cp16(vb + (uint32_t)(r * ATSH + c8 * 8) * 2, s + 2 * NC);
        }
        CP_COMMIT();
    };

    issue_kv(0, 0);

    float Oacc[16][4];
    float lsA = 0.f, lsB = 0.f;
    #pragma unroll
    for (int nt = 0; nt < 16; nt++)
        #pragma unroll
        for (int r = 0; r < 4; r++) Oacc[nt][r] = 0.f;

    for (int kt = 0; kt < NL / BNA; kt++) {
        CP_WAIT(0);        // K(kt)+V(kt) [+Q] arrived (this thread)
        __syncthreads();   // ... all threads; also: S(kt-1)/PV(kt-1) complete
                           //     -> buffers (kt+1)&1 are free to overwrite
        if (kt + 1 < NL / BNA) issue_kv((kt + 1) * BNA, (kt + 1) & 1);

        uint32_t uK = uK0 + (uint32_t)((kt & 1) * KVB_H) * 2;
        uint32_t uV = uV0 + (uint32_t)((kt & 1) * KVB_H) * 2;

        // S = Q K^T : 8 ksteps of k16 over d=128
        float Sacc[8][4];
        #pragma unroll
        for (int nt = 0; nt < 8; nt++)
            #pragma unroll
            for (int r = 0; r < 4; r++) Sacc[nt][r] = 0.f;
        #pragma unroll
        for (int ks = 0; ks < 8; ks++) {
            int k0 = ks * 16;
            uint32_t afr[4], bfr[4][4];
            LDSM_X4(afr, uQ + (uint32_t)((warpM + a_r) * ATSH + k0 + a_c) * 2);
            #pragma unroll
            for (int np = 0; np < 4; np++)
                LDSM_X4(bfr[np], uK + (uint32_t)((np * 16 + b_r) * ATSH + k0 + b_c) * 2);
            #pragma unroll
            for (int np = 0; np < 4; np++) {
                mma_bf16(Sacc[np * 2 + 0], afr, &bfr[np][0]);
                mma_bf16(Sacc[np * 2 + 1], afr, &bfr[np][2]);
            }
        }

        // P = 2^S packed straight into PV A-fragments (register-resident)
        uint32_t pfr[4][4];
        #pragma unroll
        for (int kv = 0; kv < 4; kv++) {
            #pragma unroll
            for (int t = 0; t < 2; t++) {
                int nt = 2 * kv + t;
                float e0 = ex2(Sacc[nt][0]);
                float e1 = ex2(Sacc[nt][1]);
                float e2 = ex2(Sacc[nt][2]);
                float e3 = ex2(Sacc[nt][3]);
                lsA += e0 + e1;
                lsB += e2 + e3;
                pfr[kv][2 * t + 0] = pack_bf16(e0, e1);   // row g
                pfr[kv][2 * t + 1] = pack_bf16(e2, e3);   // row g+8
            }
        }

        // O += P @ V : 4 ksteps of k16 over n=64; V via ldmatrix.trans
        #pragma unroll
        for (int kv = 0; kv < 4; kv++) {
            int k0 = kv * 16;
            #pragma unroll
            for (int dp = 0; dp < 8; dp++) {
                uint32_t vfr[4];
                LDSM_X4_T(vfr, uV + (uint32_t)((k0 + v_r) * ATSH + dp * 16 + v_c) * 2);
                mma_bf16(Oacc[dp * 2 + 0], pfr[kv], &vfr[0]);
                mma_bf16(Oacc[dp * 2 + 1], pfr[kv], &vfr[2]);
            }
        }
    }

    // lsum row reduction across the 4 q-lanes of each row-group
    lsA += __shfl_xor_sync(0xffffffffu, lsA, 1);
    lsA += __shfl_xor_sync(0xffffffffu, lsA, 2);
    lsB += __shfl_xor_sync(0xffffffffu, lsB, 1);
    lsB += __shfl_xor_sync(0xffffffffu, lsB, 2);

    // Epilogue: out = O / lsum, bf16 (flat layout == raw reshape back)
    #pragma unroll
    for (int h = 0; h < 2; h++) {
        float inv = 1.0f / (h ? lsB : lsA);
        int row = m0 + warpM + g + 8 * h;
        __nv_bfloat16* dst = outp + (size_t)bh * (NL * NCH) + (size_t)row * NCH + 2 * q;
        #pragma unroll
        for (int nt = 0; nt < 16; nt++) {
            float2 w;
            w.x = Oacc[nt][2 * h + 0] * inv;
            w.y = Oacc[nt][2 * h + 1] * inv;
            *reinterpret_cast<__nv_bfloat162*>(&dst[nt * 8]) = __float22bfloat162_rn(w);
        }
    }
}

// ---------------------------------------------------------------------------
extern "C" void kernel_launch(void* const* d_in, const int* in_sizes, int n_in,
                              void* d_out, int out_size)
{
    const float* x     = (const float*)d_in[0];
    const float* ln_g  = (const float*)d_in[1];
    const float* ln_b  = (const float*)d_in[2];
    const float* w_qkv = (const float*)d_in[3];
    const float* b_qkv = (const float*)d_in[4];
    const float* w_out = (const float*)d_in[5];
    const float* b_out = (const float*)d_in[6];
    float* out = (float*)d_out;

    float *xn;
    __nv_bfloat16 *xnh, *qkvb, *attnb, *wqkvh, *wouth;
    cudaGetSymbolAddress((void**)&xn,    g_xn);
    cudaGetSymbolAddress((void**)&xnh,   g_xnh);
    cudaGetSymbolAddress((void**)&qkvb,  g_qkv);
    cudaGetSymbolAddress((void**)&attnb, g_attn);
    cudaGetSymbolAddress((void**)&wqkvh, g_wqkvh);
    cudaGetSymbolAddress((void**)&wouth, g_wouth);

    cudaFuncSetAttribute(gemm_bf16_kernel<0>,
                         cudaFuncAttributeMaxDynamicSharedMemorySize, SMEM_GEMM);
    cudaFuncSetAttribute(gemm_bf16_kernel<1>,
                         cudaFuncAttributeMaxDynamicSharedMemorySize, SMEM_GEMM);
    cudaFuncSetAttribute(attn_kernel,
                         cudaFuncAttributeMaxDynamicSharedMemorySize, ATT_SMEM);

    // 0) Convert weights fp32 -> bf16 (native [K,N] layout)
    cvt_kernel<<<(NC * N3C) / 2048, 256>>>(w_qkv, wqkvh);
    cvt_kernel<<<(NC * NC)  / 2048, 256>>>(w_out, wouth);

    // 1) LayerNorm (fp32 + bf16 outputs)
    ln_kernel<<<NB * NL, 256>>>(x, ln_g, ln_b, xn, xnh);

    // 2) QKV projection (bf16 mma; q cols pre-scaled by log2e) -> bf16
    gemm_bf16_kernel<0><<<dim3(N3C / BN, (NB * NL) / BM), 256, SMEM_GEMM>>>(
        xnh, wqkvh, b_qkv, nullptr, qkvb, N3C);

    // 3) Attention (bf16 mma, register-resident P, 1 barrier/iter) -> bf16
    attn_kernel<<<dim3(NL / BMA, NBH), 256, ATT_SMEM>>>(qkvb, attnb);

    // 4) Output projection + bias + residual(fp32 xn) -> fp32
    gemm_bf16_kernel<1><<<dim3(NC / BN, (NB * NL) / BM), 256, SMEM_GEMM>>>(
        attnb, wouth, b_out, xn, out, NC);
}

// round 17
// speedup vs baseline: 1.0576x; 1.0301x over previous
#include <cuda_runtime.h>
#include <cuda_bf16.h>
#include <cstdint>
#include <math.h>

// Problem dims
#define NB   8
#define NL   1024
#define NC   1024
#define NH   8
#define NCH  128
#define NBH  64
#define N3C  3072
#define QK_SCALE 0.29730177875068026f  // 128^(-1/4)
#define LOG2E    1.4426950408889634f

// Scratch (allocation-free rule: __device__ globals)
__device__ __nv_bfloat16  g_xnh  [(size_t)NB * NL * NC];    // bf16 (GEMM A)
__device__ float2         g_stats[(size_t)NB * NL];         // per-row (mu, rstd)
__device__ __nv_bfloat16  g_qkv  [(size_t)NB * NL * N3C];
__device__ __nv_bfloat16  g_attn [(size_t)NB * NL * NC];
__device__ __nv_bfloat16  g_wqkvh[(size_t)NC * N3C];        // bf16, native [K,N]
__device__ __nv_bfloat16  g_wouth[(size_t)NC * NC];         // bf16, native [K,N]

// ---------------------------------------------------------------------------
// Helpers (sm_80+ PTX only; target is plain compute_103 — no 'a' features)
// ---------------------------------------------------------------------------
__device__ __forceinline__ uint32_t smem_u32(const void* p) {
    uint32_t a;
    asm("{ .reg .u64 t; cvta.to.shared.u64 t, %1; cvt.u32.u64 %0, t; }" : "=r"(a) : "l"(p));
    return a;
}
__device__ __forceinline__ void cp16(uint32_t dst, const void* src) {
    asm volatile("cp.async.cg.shared.global [%0], [%1], 16;" :: "r"(dst), "l"(src));
}
#define CP_COMMIT() asm volatile("cp.async.commit_group;" ::: "memory")
#define CP_WAIT(n)  asm volatile("cp.async.wait_group %0;" :: "n"(n) : "memory")

__device__ __forceinline__ void mma_bf16(float* d, const uint32_t* a, const uint32_t* b) {
    asm volatile("mma.sync.aligned.m16n8k16.row.col.f32.bf16.bf16.f32 "
        "{%0,%1,%2,%3}, {%4,%5,%6,%7}, {%8,%9}, {%0,%1,%2,%3};"
        : "+f"(d[0]), "+f"(d[1]), "+f"(d[2]), "+f"(d[3])
        : "r"(a[0]), "r"(a[1]), "r"(a[2]), "r"(a[3]), "r"(b[0]), "r"(b[1]));
}
#define LDSM_X4(r, addr) \
    asm volatile("ldmatrix.sync.aligned.m8n8.x4.shared.b16 {%0,%1,%2,%3}, [%4];" \
        : "=r"((r)[0]), "=r"((r)[1]), "=r"((r)[2]), "=r"((r)[3]) : "r"(addr))
#define LDSM_X4_T(r, addr) \
    asm volatile("ldmatrix.sync.aligned.m8n8.x4.trans.shared.b16 {%0,%1,%2,%3}, [%4];" \
        : "=r"((r)[0]), "=r"((r)[1]), "=r"((r)[2]), "=r"((r)[3]) : "r"(addr))

__device__ __forceinline__ float ex2(float x) {
    float r;
    asm("ex2.approx.f32 %0, %1;" : "=f"(r) : "f"(x));
    return r;
}
__device__ __forceinline__ uint32_t pack_bf16(float a, float b) {
    __nv_bfloat162 h = __float22bfloat162_rn(make_float2(a, b));
    return *(uint32_t*)&h;
}

// ---------------------------------------------------------------------------
// Fused prep kernel: LN (bf16 out + row stats; NO fp32 xn) and both weight
// fp32->bf16 conversions, dispatched by block index so they overlap.
// ---------------------------------------------------------------------------
#define LN_BLOCKS   (NB * NL)                 // 8192
#define CVT1_BLOCKS ((NC * N3C) / 2048)       // 1536
#define CVT2_BLOCKS ((NC * NC) / 2048)        // 512
#define PREP_BLOCKS (LN_BLOCKS + CVT1_BLOCKS + CVT2_BLOCKS)

__global__ void __launch_bounds__(256) prep_kernel(
    const float* __restrict__ x, const float* __restrict__ gamma,
    const float* __restrict__ beta, __nv_bfloat16* __restrict__ xnh,
    float2* __restrict__ stats,
    const float* __restrict__ wqkv, __nv_bfloat16* __restrict__ wqkvh,
    const float* __restrict__ wout, __nv_bfloat16* __restrict__ wouth)
{
    int b = blockIdx.x;
    int t = threadIdx.x;
    if (b >= LN_BLOCKS) {
        // weight conversion: 2048 elems per block (256 thr x 8)
        const float* src;
        __nv_bfloat16* dst;
        size_t i;
        if (b < LN_BLOCKS + CVT1_BLOCKS) {
            src = wqkv; dst = wqkvh;
            i = ((size_t)(b - LN_BLOCKS) * 256 + t) * 8;
        } else {
            src = wout; dst = wouth;
            i = ((size_t)(b - LN_BLOCKS - CVT1_BLOCKS) * 256 + t) * 8;
        }
        float4 a = *(const float4*)(src + i);
        float4 c = *(const float4*)(src + i + 4);
        __nv_bfloat162 h0 = __float22bfloat162_rn(make_float2(a.x, a.y));
        __nv_bfloat162 h1 = __float22bfloat162_rn(make_float2(a.z, a.w));
        __nv_bfloat162 h2 = __float22bfloat162_rn(make_float2(c.x, c.y));
        __nv_bfloat162 h3 = __float22bfloat162_rn(make_float2(c.z, c.w));
        uint4 u;
        u.x = *(uint32_t*)&h0; u.y = *(uint32_t*)&h1;
        u.z = *(uint32_t*)&h2; u.w = *(uint32_t*)&h3;
        *reinterpret_cast<uint4*>(dst + i) = u;
        return;
    }
    // LayerNorm row b
    int row = b;
    const float4* xr = reinterpret_cast<const float4*>(x + (size_t)row * NC);
    float4 v = xr[t];
    float s  = v.x + v.y + v.z + v.w;
    float ss = v.x*v.x + v.y*v.y + v.z*v.z + v.w*v.w;
    #pragma unroll
    for (int o = 16; o; o >>= 1) {
        s  += __shfl_xor_sync(0xffffffffu, s,  o);
        ss += __shfl_xor_sync(0xffffffffu, ss, o);
    }
    __shared__ float rs[8], rss[8], stat[2];
    int warp = t >> 5, lane = t & 31;
    if (lane == 0) { rs[warp] = s; rss[warp] = ss; }
    __syncthreads();
    if (t == 0) {
        float a = 0.f, b2 = 0.f;
        #pragma unroll
        for (int i = 0; i < 8; i++) { a += rs[i]; b2 += rss[i]; }
        float mu  = a * (1.0f / NC);
        float var = b2 * (1.0f / NC) - mu * mu;
        float rstd = rsqrtf(var + 1e-5f);
        stat[0] = mu;
        stat[1] = rstd;
        stats[row] = make_float2(mu, rstd);
    }
    __syncthreads();
    float mu = stat[0], rstd = stat[1];
    float4 g4 = reinterpret_cast<const float4*>(gamma)[t];
    float4 b4 = reinterpret_cast<const float4*>(beta )[t];
    float4 o;
    o.x = (v.x - mu) * rstd * g4.x + b4.x;
    o.y = (v.y - mu) * rstd * g4.y + b4.y;
    o.z = (v.z - mu) * rstd * g4.z + b4.z;
    o.w = (v.w - mu) * rstd * g4.w + b4.w;
    __nv_bfloat162 h0 = __float22bfloat162_rn(make_float2(o.x, o.y));
    __nv_bfloat162 h1 = __float22bfloat162_rn(make_float2(o.z, o.w));
    uint2 u; u.x = *(uint32_t*)&h0; u.y = *(uint32_t*)&h1;
    *reinterpret_cast<uint2*>(xnh + (size_t)row * NC + t * 4) = u;
}

// ---------------------------------------------------------------------------
// bf16 mma.sync GEMM: C = A[M,K] @ B[K,N] (+bias; MODE epilogue)
// CTA 128x128, BK=64, 8 warps (2x4), warp 64x32, 3-stage cp.async, single
// barrier per chunk, fragment double-buffering across k-steps.
// MODE 0: bf16 out, q cols *= QK_SCALE*LOG2E, k cols *= QK_SCALE.
// MODE 1: fp32 out, += bias + RECOMPUTED LN residual (x,stats,gamma,beta).
// ---------------------------------------------------------------------------
#define BM 128
#define BN 128
#define BK 64
#define KTOT 1024
#define NCHUNK (KTOT / BK)              // 16
#define GST 72                          // A smem halves stride (64+8)
#define BNS 136                         // B smem halves stride (128+8)
#define STAGE_H (BM * GST + BK * BNS)   // 17920 halves
#define SMEM_GEMM (3 * STAGE_H * 2)     // 107520 bytes

template <int MODE>
__global__ void __launch_bounds__(256, 2) gemm_bf16_kernel(
    const __nv_bfloat16* __restrict__ A, const __nv_bfloat16* __restrict__ Bw,
    const float* __restrict__ bias, const float* __restrict__ xres,
    const float* __restrict__ gamma, const float* __restrict__ beta,
    const float2* __restrict__ stats,
    void* __restrict__ Cm, int N)
{
    extern __shared__ __align__(16) __nv_bfloat16 smh[];
    uint32_t sbase = smem_u32(smh);
    int tid = threadIdx.x;
    int wid = tid >> 5, lane = tid & 31;
    int g = lane >> 2, q = lane & 3;
    const int bm = blockIdx.y * BM;
    const int bn = blockIdx.x * BN;
    const int warpM = (wid >> 2) * 64;
    const int warpN = (wid & 3) * 32;

    int a_r = (lane & 7) | (((lane >> 3) & 1) << 3);
    int a_c = (lane >> 4) << 3;
    int v_r = (lane & 7) | (((lane >> 3) & 1) << 3);
    int v_c = (lane >> 4) << 3;

    auto load_chunk = [&](int kk, int stg) {
        uint32_t sA = sbase + (uint32_t)(stg * STAGE_H) * 2;
        uint32_t sB = sA + (uint32_t)(BM * GST) * 2;
        #pragma unroll
        for (int i = 0; i < 4; i++) {
            int f = i * 256 + tid;
            int r = f >> 3, c = f & 7;
            cp16(sA + (uint32_t)(r * GST + c * 8) * 2,
                 A + (size_t)(bm + r) * KTOT + kk + c * 8);
        }
        #pragma unroll
        for (int i = 0; i < 4; i++) {
            int f = i * 256 + tid;
            int r = f >> 4, c = f & 15;
            cp16(sB + (uint32_t)(r * BNS + c * 8) * 2,
                 Bw + (size_t)(kk + r) * N + bn + c * 8);
        }
        CP_COMMIT();
    };

    float accf[4][4][4];
    #pragma unroll
    for (int mt = 0; mt < 4; mt++)
        #pragma unroll
        for (int nt = 0; nt < 4; nt++)
            #pragma unroll
            for (int r = 0; r < 4; r++) accf[mt][nt][r] = 0.f;

    load_chunk(0, 0);
    load_chunk(BK, 1);

    for (int c = 0; c < NCHUNK; c++) {
        if (c < NCHUNK - 1) CP_WAIT(1); else CP_WAIT(0);
        __syncthreads();
        if (c + 2 < NCHUNK) load_chunk((c + 2) * BK, (c + 2) % 3);
        uint32_t sA = sbase + (uint32_t)((c % 3) * STAGE_H) * 2;
        uint32_t sB = sA + (uint32_t)(BM * GST) * 2;
        uint32_t aAddr = sA + (uint32_t)((warpM + a_r) * GST + a_c) * 2;
        uint32_t bAddr = sB + (uint32_t)(v_r * BNS + warpN + v_c) * 2;

        uint32_t afr[2][4][4], bfr[2][2][4];
        #pragma unroll
        for (int mt = 0; mt < 4; mt++)
            LDSM_X4(afr[0][mt], aAddr + (uint32_t)(mt * 16 * GST) * 2);
        #pragma unroll
        for (int np = 0; np < 2; np++)
            LDSM_X4_T(bfr[0][np], bAddr + (uint32_t)(np * 16) * 2);

        #pragma unroll
        for (int ks = 0; ks < 4; ks++) {
            int cur = ks & 1, nxt = cur ^ 1;
            if (ks < 3) {
                uint32_t aA = aAddr + (uint32_t)((ks + 1) * 16) * 2;
                uint32_t bA = bAddr + (uint32_t)((ks + 1) * 16 * BNS) * 2;
                #pragma unroll
                for (int mt = 0; mt < 4; mt++)
                    LDSM_X4(afr[nxt][mt], aA + (uint32_t)(mt * 16 * GST) * 2);
                #pragma unroll
                for (int np = 0; np < 2; np++)
                    LDSM_X4_T(bfr[nxt][np], bA + (uint32_t)(np * 16) * 2);
            }
            #pragma unroll
            for (int mt = 0; mt < 4; mt++)
                #pragma unroll
                for (int np = 0; np < 2; np++) {
                    mma_bf16(accf[mt][np * 2 + 0], afr[cur][mt], &bfr[cur][np][0]);
                    mma_bf16(accf[mt][np * 2 + 1], afr[cur][mt], &bfr[cur][np][2]);
                }
        }
    }

    #pragma unroll
    for (int mt = 0; mt < 4; mt++) {
        int row0 = bm + warpM + mt * 16 + g;
        #pragma unroll
        for (int nt = 0; nt < 4; nt++) {
            int col = bn + warpN + nt * 8 + q * 2;
            float2 bb = *(const float2*)&bias[col];
            float mscale = 1.0f;
            float2 gg, be;
            if (MODE == 0) {
                mscale = (col < NC) ? (QK_SCALE * LOG2E)
                                    : ((col < 2 * NC) ? QK_SCALE : 1.0f);
            } else {
                gg = *(const float2*)&gamma[col];
                be = *(const float2*)&beta[col];
            }
            #pragma unroll
            for (int h = 0; h < 2; h++) {
                int row = row0 + h * 8;
                float2 o;
                o.x = accf[mt][nt][h * 2 + 0] + bb.x;
                o.y = accf[mt][nt][h * 2 + 1] + bb.y;
                if (MODE == 0) {
                    o.x *= mscale; o.y *= mscale;
                    __nv_bfloat162 hb = __float22bfloat162_rn(o);
                    *reinterpret_cast<__nv_bfloat162*>(
                        (__nv_bfloat16*)Cm + (size_t)row * N + col) = hb;
                } else {
                    float2 xv = *(const float2*)&xres[(size_t)row * NC + col];
                    float2 st = stats[row];
                    o.x += (xv.x - st.x) * st.y * gg.x + be.x;
                    o.y += (xv.y - st.x) * st.y * gg.y + be.y;
                    *reinterpret_cast<float2*>((float*)Cm + (size_t)row * N + col) = o;
                }
            }
        }
    }
}

// ---------------------------------------------------------------------------
// bf16 mma.sync flash attention v2 (verified R16): RAW-RESHAPED layout,
// no-max log2 softmax, register-resident P, K/V double-buffered,
// one __syncthreads per kv-iteration.
// ---------------------------------------------------------------------------
#define BMA 128
#define BNA 64
#define ATSH 136                       // smem halves stride (128+8)
#define KVB_H (BNA * ATSH)             // 8704 halves per K or V buffer
#define QOFFH  0
#define K0OFFH (BMA * ATSH)            // 17408
#define V0OFFH (K0OFFH + 2 * KVB_H)    // 34816
#define ATT_SMEM ((V0OFFH + 2 * KVB_H) * 2)   // 104448 B

__global__ void __launch_bounds__(256, 2) attn_kernel(
    const __nv_bfloat16* __restrict__ qkv, __nv_bfloat16* __restrict__ outp)
{
    extern __shared__ __align__(16) __nv_bfloat16 smh[];
    uint32_t uQ  = smem_u32(smh + QOFFH);
    uint32_t uK0 = smem_u32(smh + K0OFFH);
    uint32_t uV0 = smem_u32(smh + V0OFFH);

    int tid = threadIdx.x;
    int wid = tid >> 5, lane = tid & 31;
    int g = lane >> 2, q = lane & 3;
    int bh  = blockIdx.y;
    int m0  = blockIdx.x * BMA;
    int bb  = bh >> 3, hh = bh & 7;
    const __nv_bfloat16* base = qkv + (size_t)(bb * 1024 + hh * 128) * N3C;
    const int warpM = wid * 16;

    int a_r = (lane & 7) | (((lane >> 3) & 1) << 3);
    int a_c = (lane >> 4) << 3;
    int b_r = (lane & 7) | (((lane >> 4) & 1) << 3);
    int b_c = ((lane >> 3) & 1) << 3;
    int v_r = (lane & 7) | (((lane >> 3) & 1) << 3);
    int v_c = (lane >> 4) << 3;

    // Q tile -> smem via cp.async (group 1)
    #pragma unroll
    for (int i = 0; i < 8; i++) {
        int f = i * 256 + tid;
        int r = f >> 4, c8 = f & 15;
        int l2 = m0 + r;
        cp16(uQ + (uint32_t)(r * ATSH + c8 * 8) * 2,
             base + (size_t)(l2 >> 3) * N3C + ((l2 & 7) << 7) + c8 * 8);
    }
    CP_COMMIT();

    // K+V for a kv-tile -> buffer buf, as ONE commit group
    auto issue_kv = [&](int n0, int buf) {
        uint32_t kb = uK0 + (uint32_t)(buf * KVB_H) * 2;
        uint32_t vb = uV0 + (uint32_t)(buf * KVB_H) * 2;
        #pragma unroll
        for (int i = 0; i < 4; i++) {
            int f = i * 256 + tid;
            int r = f >> 4, c8 = f & 15;
            int n = n0 + r;
            const __nv_bfloat16* s =
                base + (size_t)(n >> 3) * N3C + ((n & 7) << 7) + c8 * 8;
            cp16(kb + (uint32_t)(r * ATSH + c8 * 8) * 2, s + NC);
            cp16(vb + (uint32_t)(r * ATSH + c8 * 8) * 2, s + 2 * NC);
        }
        CP_COMMIT();
    };

    issue_kv(0, 0);

    float Oacc[16][4];
    float lsA = 0.f, lsB = 0.f;
    #pragma unroll
    for (int nt = 0; nt < 16; nt++)
        #pragma unroll
        for (int r = 0; r < 4; r++) Oacc[nt][r] = 0.f;

    for (int kt = 0; kt < NL / BNA; kt++) {
        CP_WAIT(0);        // K(kt)+V(kt) [+Q] arrived (this thread)
        __syncthreads();   // ... all threads; also: S(kt-1)/PV(kt-1) complete
        if (kt + 1 < NL / BNA) issue_kv((kt + 1) * BNA, (kt + 1) & 1);

        uint32_t uK = uK0 + (uint32_t)((kt & 1) * KVB_H) * 2;
        uint32_t uV = uV0 + (uint32_t)((kt & 1) * KVB_H) * 2;

        // S = Q K^T : 8 ksteps of k16 over d=128
        float Sacc[8][4];
        #pragma unroll
        for (int nt = 0; nt < 8; nt++)
            #pragma unroll
            for (int r = 0; r < 4; r++) Sacc[nt][r] = 0.f;
        #pragma unroll
        for (int ks = 0; ks < 8; ks++) {
            int k0 = ks * 16;
            uint32_t afr[4], bfr[4][4];
            LDSM_X4(afr, uQ + (uint32_t)((warpM + a_r) * ATSH + k0 + a_c) * 2);
            #pragma unroll
            for (int np = 0; np < 4; np++)
                LDSM_X4(bfr[np], uK + (uint32_t)((np * 16 + b_r) * ATSH + k0 + b_c) * 2);
            #pragma unroll
            for (int np = 0; np < 4; np++) {
                mma_bf16(Sacc[np * 2 + 0], afr, &bfr[np][0]);
                mma_bf16(Sacc[np * 2 + 1], afr, &bfr[np][2]);
            }
        }

        // P = 2^S packed straight into PV A-fragments (register-resident)
        uint32_t pfr[4][4];
        #pragma unroll
        for (int kv = 0; kv < 4; kv++) {
            #pragma unroll
            for (int t = 0; t < 2; t++) {
                int nt = 2 * kv + t;
                float e0 = ex2(Sacc[nt][0]);
                float e1 = ex2(Sacc[nt][1]);
                float e2 = ex2(Sacc[nt][2]);
                float e3 = ex2(Sacc[nt][3]);
                lsA += e0 + e1;
                lsB += e2 + e3;
                pfr[kv][2 * t + 0] = pack_bf16(e0, e1);   // row g
                pfr[kv][2 * t + 1] = pack_bf16(e2, e3);   // row g+8
            }
        }

        // O += P @ V : 4 ksteps of k16 over n=64; V via ldmatrix.trans
        #pragma unroll
        for (int kv = 0; kv < 4; kv++) {
            int k0 = kv * 16;
            #pragma unroll
            for (int dp = 0; dp < 8; dp++) {
                uint32_t vfr[4];
                LDSM_X4_T(vfr, uV + (uint32_t)((k0 + v_r) * ATSH + dp * 16 + v_c) * 2);
                mma_bf16(Oacc[dp * 2 + 0], pfr[kv], &vfr[0]);
                mma_bf16(Oacc[dp * 2 + 1], pfr[kv], &vfr[2]);
            }
        }
    }

    // lsum row reduction across the 4 q-lanes of each row-group
    lsA += __shfl_xor_sync(0xffffffffu, lsA, 1);
    lsA += __shfl_xor_sync(0xffffffffu, lsA, 2);
    lsB += __shfl_xor_sync(0xffffffffu, lsB, 1);
    lsB += __shfl_xor_sync(0xffffffffu, lsB, 2);

    // Epilogue: out = O / lsum, bf16 (flat layout == raw reshape back)
    #pragma unroll
    for (int h = 0; h < 2; h++) {
        float inv = 1.0f / (h ? lsB : lsA);
        int row = m0 + warpM + g + 8 * h;
        __nv_bfloat16* dst = outp + (size_t)bh * (NL * NCH) + (size_t)row * NCH + 2 * q;
        #pragma unroll
        for (int nt = 0; nt < 16; nt++) {
            float2 w;
            w.x = Oacc[nt][2 * h + 0] * inv;
            w.y = Oacc[nt][2 * h + 1] * inv;
            *reinterpret_cast<__nv_bfloat162*>(&dst[nt * 8]) = __float22bfloat162_rn(w);
        }
    }
}

// ---------------------------------------------------------------------------
extern "C" void kernel_launch(void* const* d_in, const int* in_sizes, int n_in,
                              void* d_out, int out_size)
{
    const float* x     = (const float*)d_in[0];
    const float* ln_g  = (const float*)d_in[1];
    const float* ln_b  = (const float*)d_in[2];
    const float* w_qkv = (const float*)d_in[3];
    const float* b_qkv = (const float*)d_in[4];
    const float* w_out = (const float*)d_in[5];
    const float* b_out = (const float*)d_in[6];
    float* out = (float*)d_out;

    __nv_bfloat16 *xnh, *qkvb, *attnb, *wqkvh, *wouth;
    float2 *stats;
    cudaGetSymbolAddress((void**)&xnh,   g_xnh);
    cudaGetSymbolAddress((void**)&stats, g_stats);
    cudaGetSymbolAddress((void**)&qkvb,  g_qkv);
    cudaGetSymbolAddress((void**)&attnb, g_attn);
    cudaGetSymbolAddress((void**)&wqkvh, g_wqkvh);
    cudaGetSymbolAddress((void**)&wouth, g_wouth);

    cudaFuncSetAttribute(gemm_bf16_kernel<0>,
                         cudaFuncAttributeMaxDynamicSharedMemorySize, SMEM_GEMM);
    cudaFuncSetAttribute(gemm_bf16_kernel<1>,
                         cudaFuncAttributeMaxDynamicSharedMemorySize, SMEM_GEMM);
    cudaFuncSetAttribute(attn_kernel,
                         cudaFuncAttributeMaxDynamicSharedMemorySize, ATT_SMEM);

    // 1) Fused prep: LN (bf16 + stats) and weight conversions, one launch
    prep_kernel<<<PREP_BLOCKS, 256>>>(x, ln_g, ln_b, xnh, stats,
                                      w_qkv, wqkvh, w_out, wouth);

    // 2) QKV projection (bf16 mma; q cols pre-scaled by log2e) -> bf16
    gemm_bf16_kernel<0><<<dim3(N3C / BN, (NB * NL) / BM), 256, SMEM_GEMM>>>(
        xnh, wqkvh, b_qkv, nullptr, nullptr, nullptr, nullptr, qkvb, N3C);

    // 3) Attention (bf16 mma, register-resident P, 1 barrier/iter) -> bf16
    attn_kernel<<<dim3(NL / BMA, NBH), 256, ATT_SMEM>>>(qkvb, attnb);

    // 4) Output projection + bias + recomputed LN residual -> fp32
    gemm_bf16_kernel<1><<<dim3(NC / BN, (NB * NL) / BM), 256, SMEM_GEMM>>>(
        attnb, wouth, b_out, x, ln_g, ln_b, stats, out, NC);
}